// round 5
// baseline (speedup 1.0000x reference)
#include <cuda_runtime.h>

// Problem shape (fixed by dataset): source [B,N,3], target [B,M,3], fp32.
#define Bq 2
#define Nq 8192
#define Mq 8192
#define THREADS 256
#define S_PT 2                                  // sources per thread
#define SRC_PER_BLOCK (THREADS * S_PT)          // 512
#define NCHUNK 64                               // target chunks
#define CHUNK (Mq / NCHUNK)                     // 128 targets per chunk
#define SRCBLK_PER_B (Nq / SRC_PER_BLOCK)       // 16
#define NSRCBLK (Bq * SRCBLK_PER_B)             // 32
#define NBLOCKS (NCHUNK * NSRCBLK)              // 2048
#define BN (Bq * Nq)                            // 16384 sources total

// Scratch (no allocations allowed). g_enc zero-init == identity for the
// descending-encoded max (== float min); the tail block resets it to 0 for
// the next graph replay. g_ticket likewise self-resets.
__device__ unsigned int g_enc[BN];
__device__ int g_ticket;

// ---- packed f32x2 helpers (sm_100+; must be inline PTX) ----
__device__ __forceinline__ unsigned long long pack2(float a, float b) {
    unsigned long long r;
    asm("mov.b64 %0, {%1, %2};" : "=l"(r) : "f"(a), "f"(b));
    return r;
}
__device__ __forceinline__ unsigned long long fma2(unsigned long long a,
                                                   unsigned long long b,
                                                   unsigned long long c) {
    unsigned long long d;
    asm("fma.rn.f32x2 %0, %1, %2, %3;" : "=l"(d) : "l"(a), "l"(b), "l"(c));
    return d;
}
__device__ __forceinline__ float lo2(unsigned long long v) {
    return __uint_as_float((unsigned int)v);
}
__device__ __forceinline__ float hi2(unsigned long long v) {
    return __uint_as_float((unsigned int)(v >> 32));
}

// Descending order-preserving float->uint encoding: x1 < x2  <=>  enc(x1) > enc(x2).
// Identity for max is 0 (any finite float encodes > 0) -> zero-init is correct.
__device__ __forceinline__ unsigned int enc_desc(float x) {
    unsigned int u = __float_as_uint(x);
    return (u & 0x80000000u) ? u : (~u & 0x7FFFFFFFu);
}

// Single fused kernel. Each block: 512 sources x 128 targets.
// d' = 0.5*||t||^2 - s.t  tracked packed (2 targets per fma.rn.f32x2),
// 4 targets per inner iteration via 16B shared loads.
// Per-source min folded globally via RED.MAX.U32 on the descending encoding
// (exact, order-independent -> deterministic). Ticketed last block decodes,
// adds ||s||^2, tree-sums -> mean loss.
__global__ __launch_bounds__(THREADS, 6) void nn_fused_kernel(
    const float* __restrict__ src, const float* __restrict__ tgt,
    float* __restrict__ out) {
    __shared__ __align__(16) float stx[CHUNK];
    __shared__ __align__(16) float sty[CHUNK];
    __shared__ __align__(16) float stz[CHUNK];
    __shared__ __align__(16) float sh2[CHUNK];
    __shared__ float red[THREADS];
    __shared__ bool is_last;

    const int tid = threadIdx.x;
    const int c = blockIdx.x;                       // target chunk
    const int sb = blockIdx.y;                      // source block
    const int b = sb / SRCBLK_PER_B;
    const int src0 = (sb % SRCBLK_PER_B) * SRC_PER_BLOCK;

    // Build this chunk's target SoA (+ ht2 = 0.5*||t||^2) in smem from AoS.
    const float* tbase = tgt + (b * Mq + c * CHUNK) * 3;
#pragma unroll
    for (int i = tid; i < CHUNK * 3; i += THREADS) {
        float v = tbase[i];
        int j = i / 3, d = i % 3;
        (d == 0 ? stx : (d == 1 ? sty : stz))[j] = v;
    }
    __syncthreads();
    if (tid < CHUNK) {
        float x = stx[tid], y = sty[tid], z = stz[tid];
        sh2[tid] = 0.5f * (x * x + y * y + z * z);
    }
    __syncthreads();

    // Per-thread sources: negated + broadcast-packed once.
    unsigned long long nsx[S_PT], nsy[S_PT], nsz[S_PT];
#pragma unroll
    for (int s = 0; s < S_PT; s++) {
        int gi = b * Nq + src0 + s * THREADS + tid;
        float x = src[gi * 3 + 0];
        float y = src[gi * 3 + 1];
        float z = src[gi * 3 + 2];
        nsx[s] = pack2(-x, -x);
        nsy[s] = pack2(-y, -y);
        nsz[s] = pack2(-z, -z);
    }

    float m0[S_PT], m1[S_PT];
#pragma unroll
    for (int s = 0; s < S_PT; s++) {
        m0[s] = __int_as_float(0x7f800000);
        m1[s] = __int_as_float(0x7f800000);
    }

    const ulonglong2* px = (const ulonglong2*)stx;  // 16B = 4 targets (2 packed)
    const ulonglong2* py = (const ulonglong2*)sty;
    const ulonglong2* pz = (const ulonglong2*)stz;
    const ulonglong2* ph = (const ulonglong2*)sh2;

#pragma unroll 4
    for (int jp = 0; jp < CHUNK / 4; jp++) {
        ulonglong2 tx = px[jp];   // single LDS.128 broadcast
        ulonglong2 ty = py[jp];
        ulonglong2 tz = pz[jp];
        ulonglong2 h  = ph[jp];
#pragma unroll
        for (int s = 0; s < S_PT; s++) {
            unsigned long long d0 = fma2(nsx[s], tx.x, h.x);
            unsigned long long d1 = fma2(nsx[s], tx.y, h.y);
            d0 = fma2(nsy[s], ty.x, d0);
            d1 = fma2(nsy[s], ty.y, d1);
            d0 = fma2(nsz[s], tz.x, d0);
            d1 = fma2(nsz[s], tz.y, d1);
            m0[s] = fminf(m0[s], lo2(d0));
            m1[s] = fminf(m1[s], hi2(d0));
            m0[s] = fminf(m0[s], lo2(d1));
            m1[s] = fminf(m1[s], hi2(d1));
        }
    }

    // Fold this chunk's per-source min into the global min (RED.MAX.U32).
#pragma unroll
    for (int s = 0; s < S_PT; s++) {
        int gi = b * Nq + src0 + s * THREADS + tid;
        atomicMax(&g_enc[gi], enc_desc(fminf(m0[s], m1[s])));
    }

    // Ticket: last block of the whole grid finishes the job.
    __threadfence();
    __syncthreads();
    if (tid == 0) {
        int t = atomicAdd(&g_ticket, 1);
        is_last = (t == NBLOCKS - 1);
    }
    __syncthreads();
    if (!is_last) return;

    __threadfence();
    float acc = 0.0f;
#pragma unroll 4
    for (int k = 0; k < BN / THREADS; k++) {
        int gi = k * THREADS + tid;
        unsigned int e = __ldcg(&g_enc[gi]);          // L2 read (skip stale L1)
        unsigned int u = (e & 0x80000000u) ? e : (~e & 0x7FFFFFFFu);
        float mn = __uint_as_float(u);
        float x = src[gi * 3 + 0];
        float y = src[gi * 3 + 1];
        float z = src[gi * 3 + 2];
        acc += x * x + y * y + z * z + 2.0f * mn;     // ||s - t*||^2
    }
    red[tid] = acc;
    __syncthreads();
#pragma unroll
    for (int o = THREADS / 2; o > 0; o >>= 1) {
        if (tid < o) red[tid] += red[tid + o];
        __syncthreads();
    }
    if (tid == 0) {
        out[0] = red[0] * (1.0f / (float)(Bq * Nq * 3));
        g_ticket = 0;                                 // reset for next replay
    }
    // Reset g_enc to the max-identity (0) for the next replay.
#pragma unroll 4
    for (int k = 0; k < BN / THREADS; k++)
        g_enc[k * THREADS + tid] = 0u;
}

extern "C" void kernel_launch(void* const* d_in, const int* in_sizes, int n_in,
                              void* d_out, int out_size) {
    const float* src = (const float*)d_in[0];   // source_point_cloud [B,N,3]
    const float* tgt = (const float*)d_in[1];   // target_point_cloud [B,M,3]
    (void)in_sizes; (void)n_in; (void)out_size;

    nn_fused_kernel<<<dim3(NCHUNK, NSRCBLK), THREADS>>>(src, tgt, (float*)d_out);
}

// round 6
// speedup vs baseline: 1.0738x; 1.0738x over previous
#include <cuda_runtime.h>

// Problem shape (fixed by dataset): source [B,N,3], target [B,M,3], fp32.
#define Bq 2
#define Nq 8192
#define Mq 8192
#define THREADS 256
#define S_PT 8                                  // sources per thread (lane-resident side)
#define SRC_PER_BLOCK (THREADS * S_PT)          // 2048
#define NCHUNK 128                              // target chunks
#define CHUNK (Mq / NCHUNK)                     // 64 targets per chunk
#define SRCBLK_PER_B (Nq / SRC_PER_BLOCK)       // 4
#define NSRCBLK (Bq * SRCBLK_PER_B)             // 8
#define NBLOCKS (NCHUNK * NSRCBLK)              // 1024
#define BN (Bq * Nq)                            // 16384 sources total

// Scratch (no allocations allowed). g_enc zero-init == identity for the
// descending-encoded max (== float min); the tail block resets it to 0 for
// the next graph replay. g_ticket likewise self-resets.
__device__ unsigned int g_enc[BN];
__device__ int g_ticket;

// ---- packed f32x2 helpers (sm_100+; must be inline PTX) ----
__device__ __forceinline__ unsigned long long pack2(float a, float b) {
    unsigned long long r;
    asm("mov.b64 %0, {%1, %2};" : "=l"(r) : "f"(a), "f"(b));
    return r;
}
__device__ __forceinline__ unsigned long long fma2(unsigned long long a,
                                                   unsigned long long b,
                                                   unsigned long long c) {
    unsigned long long d;
    asm("fma.rn.f32x2 %0, %1, %2, %3;" : "=l"(d) : "l"(a), "l"(b), "l"(c));
    return d;
}
__device__ __forceinline__ float lo2(unsigned long long v) {
    return __uint_as_float((unsigned int)v);
}
__device__ __forceinline__ float hi2(unsigned long long v) {
    return __uint_as_float((unsigned int)(v >> 32));
}

// Descending order-preserving float->uint encoding: x1 < x2  <=>  enc(x1) > enc(x2).
// Identity for max is 0 -> zero-init is correct.
__device__ __forceinline__ unsigned int enc_desc(float x) {
    unsigned int u = __float_as_uint(x);
    return (u & 0x80000000u) ? u : (~u & 0x7FFFFFFFu);
}

// Single fused kernel. Each block: 2048 sources x 64 targets.
// d' = 0.5*||t||^2 - s.t  tracked packed (2 targets per fma.rn.f32x2).
// S_PT=8 amortizes the smem-broadcast writeback (512B/LDS.128) 8 ways.
// Per-source min folded globally via RED.MAX.U32 on the descending encoding
// (exact, order-independent -> deterministic). Ticketed last block decodes,
// adds ||s||^2, tree-sums -> mean loss.
__global__ __launch_bounds__(THREADS, 3) void nn_fused_kernel(
    const float* __restrict__ src, const float* __restrict__ tgt,
    float* __restrict__ out) {
    __shared__ __align__(16) float stx[CHUNK];
    __shared__ __align__(16) float sty[CHUNK];
    __shared__ __align__(16) float stz[CHUNK];
    __shared__ __align__(16) float sh2[CHUNK];
    __shared__ float red[THREADS];
    __shared__ bool is_last;

    const int tid = threadIdx.x;
    const int c = blockIdx.x;                       // target chunk
    const int sb = blockIdx.y;                      // source block
    const int b = sb / SRCBLK_PER_B;
    const int src0 = (sb % SRCBLK_PER_B) * SRC_PER_BLOCK;

    // Build this chunk's target SoA (+ ht2 = 0.5*||t||^2) in smem from AoS.
    const float* tbase = tgt + (b * Mq + c * CHUNK) * 3;
    if (tid < CHUNK * 3) {
        float v = tbase[tid];
        int j = tid / 3, d = tid % 3;
        (d == 0 ? stx : (d == 1 ? sty : stz))[j] = v;
    }
    __syncthreads();
    if (tid < CHUNK) {
        float x = stx[tid], y = sty[tid], z = stz[tid];
        sh2[tid] = 0.5f * (x * x + y * y + z * z);
    }

    // Per-thread sources: negated + broadcast-packed once (48 regs).
    unsigned long long nsx[S_PT], nsy[S_PT], nsz[S_PT];
#pragma unroll
    for (int s = 0; s < S_PT; s++) {
        int gi = b * Nq + src0 + s * THREADS + tid;
        float x = src[gi * 3 + 0];
        float y = src[gi * 3 + 1];
        float z = src[gi * 3 + 2];
        nsx[s] = pack2(-x, -x);
        nsy[s] = pack2(-y, -y);
        nsz[s] = pack2(-z, -z);
    }

    float m[S_PT];
#pragma unroll
    for (int s = 0; s < S_PT; s++) m[s] = __int_as_float(0x7f800000);

    __syncthreads();

    const ulonglong2* px = (const ulonglong2*)stx;  // 16B = 4 targets (2 packed)
    const ulonglong2* py = (const ulonglong2*)sty;
    const ulonglong2* pz = (const ulonglong2*)stz;
    const ulonglong2* ph = (const ulonglong2*)sh2;

#pragma unroll 1
    for (int jp = 0; jp < CHUNK / 4; jp++) {
        ulonglong2 tx = px[jp];   // broadcast LDS.128
        ulonglong2 ty = py[jp];
        ulonglong2 tz = pz[jp];
        ulonglong2 h  = ph[jp];
#pragma unroll
        for (int s = 0; s < S_PT; s++) {
            unsigned long long d0 = fma2(nsx[s], tx.x, h.x);
            unsigned long long d1 = fma2(nsx[s], tx.y, h.y);
            d0 = fma2(nsy[s], ty.x, d0);
            d1 = fma2(nsy[s], ty.y, d1);
            d0 = fma2(nsz[s], tz.x, d0);
            d1 = fma2(nsz[s], tz.y, d1);
            float a0 = fminf(lo2(d0), hi2(d0));
            float a1 = fminf(lo2(d1), hi2(d1));
            m[s] = fminf(m[s], fminf(a0, a1));
        }
    }

    // Fold this block's per-source min into the global min (RED.MAX.U32).
#pragma unroll
    for (int s = 0; s < S_PT; s++) {
        int gi = b * Nq + src0 + s * THREADS + tid;
        atomicMax(&g_enc[gi], enc_desc(m[s]));
    }

    // Ticket: last block of the whole grid finishes the job.
    __threadfence();
    __syncthreads();
    if (tid == 0) {
        int t = atomicAdd(&g_ticket, 1);
        is_last = (t == NBLOCKS - 1);
    }
    __syncthreads();
    if (!is_last) return;

    __threadfence();
    float acc = 0.0f;
#pragma unroll 8
    for (int k = 0; k < BN / THREADS; k++) {
        int gi = k * THREADS + tid;
        unsigned int e = __ldcg(&g_enc[gi]);          // L2 read (skip stale L1)
        unsigned int u = (e & 0x80000000u) ? e : (~e & 0x7FFFFFFFu);
        float mn = __uint_as_float(u);
        float x = src[gi * 3 + 0];
        float y = src[gi * 3 + 1];
        float z = src[gi * 3 + 2];
        acc += x * x + y * y + z * z + 2.0f * mn;     // ||s - t*||^2
    }
    red[tid] = acc;
    __syncthreads();
#pragma unroll
    for (int o = THREADS / 2; o > 0; o >>= 1) {
        if (tid < o) red[tid] += red[tid + o];
        __syncthreads();
    }
    if (tid == 0) {
        out[0] = red[0] * (1.0f / (float)(Bq * Nq * 3));
        g_ticket = 0;                                 // reset for next replay
    }
    // Reset g_enc to the max-identity (0) for the next replay.
#pragma unroll 8
    for (int k = 0; k < BN / THREADS; k++)
        g_enc[k * THREADS + tid] = 0u;
}

extern "C" void kernel_launch(void* const* d_in, const int* in_sizes, int n_in,
                              void* d_out, int out_size) {
    const float* src = (const float*)d_in[0];   // source_point_cloud [B,N,3]
    const float* tgt = (const float*)d_in[1];   // target_point_cloud [B,M,3]
    (void)in_sizes; (void)n_in; (void)out_size;

    nn_fused_kernel<<<dim3(NCHUNK, NSRCBLK), THREADS>>>(src, tgt, (float*)d_out);
}